// round 14
// baseline (speedup 1.0000x reference)
#include <cuda_runtime.h>
#include <cuda_bf16.h>
#include <cuda_fp16.h>
#include <cstdint>

#define NN 4096
#define FIN 128
#define FO 64
#define HH 4
#define CC 512   // 256 proj cols (h*64+o) + 256 skip cols

// ---------------- scratch (static device globals; no allocation) ----------------
__device__ uint32_t g_em[(size_t)NN * NN / 2];     // exp(mask) bf16 pairs (32 MB)
__device__ float    g_hidden[(size_t)NN * CC];     // [n][c]: c<256 proj, c>=256 skip (8 MB)
__device__ float    g_Wc[FIN * CC];                // combined weights [f][c]
__device__ float4   g_A[HH * NN];                  // per (h,i): a, e^a, e^{0.2a}, -
__device__ float4   g_B[HH * NN];                  // per (h,j): b, e^b, e^{0.2b}, -
__device__ uint32_t g_projT[(size_t)256 * (NN/2)]; // projT fp16 pairs: row c=h*64+f, cols j (2 MB)
__device__ uint2    g_Bp[HH * NN];                 // packed bf16 (thr,e1),(e2,0) per (h,j)
__device__ float    g_Zp[4][2][HH * NN];           // k5 row-chunk partial column sums (512 KB)
__device__ float    g_part[(size_t)4 * NN * 256];  // per-j-chunk partial outputs (16 MB)

// ---------------- helpers ----------------
__device__ __forceinline__ float maskf(float d, float b, float cut) {
    float wdm = d + b;
    return wdm > 0.f ? wdm : (b > cut ? (b + wdm) : -1e9f);
}
__device__ __forceinline__ uint32_t packbf2(float lo, float hi) {
    __nv_bfloat162 p = __floats2bfloat162_rn(lo, hi);
    return *(uint32_t*)&p;
}
__device__ __forceinline__ uint32_t packh2(float lo, float hi) {
    __half2 p = __floats2half2_rn(lo, hi);
    return *(uint32_t*)&p;
}
__device__ __forceinline__ uint32_t smem_u32(const void* p) {
    uint32_t a;
    asm("{ .reg .u64 t; cvta.to.shared.u64 t, %1; cvt.u32.u64 %0, t; }" : "=r"(a) : "l"(p));
    return a;
}
__device__ __forceinline__ void ldsm4(uint32_t& r0, uint32_t& r1, uint32_t& r2, uint32_t& r3,
                                      uint32_t addr) {
    asm volatile("ldmatrix.sync.aligned.m8n8.x4.shared.b16 {%0,%1,%2,%3}, [%4];"
                 : "=r"(r0), "=r"(r1), "=r"(r2), "=r"(r3) : "r"(addr));
}
__device__ __forceinline__ void cpasync16(uint32_t saddr, const void* gaddr) {
    asm volatile("cp.async.cg.shared.global [%0], [%1], 16;" :: "r"(saddr), "l"(gaddr));
}

// ---------------- K0: build combined weight matrix Wc[f][c] ----------------
__global__ void k0_weights(const float* __restrict__ projp, const float* __restrict__ skw) {
    int idx = blockIdx.x * 256 + threadIdx.x;
    int f = idx >> 9, c = idx & 511;
    float v;
    if (c < 256) v = projp[(c >> 6) * (FIN * FO) + f * FO + (c & 63)];
    else         v = skw[(c - 256) * FIN + f];
    g_Wc[idx] = v;
}

// ---------------- K1: hidden = nodes @ Wc; fused per-(h,n) scores for head tiles ----------------
__global__ void __launch_bounds__(256) k1_gemm(const float* __restrict__ nodes,
                                               const float* __restrict__ ssrc,
                                               const float* __restrict__ stgt) {
    __shared__ float pool[12288];          // 48 KB: sN[4096] | sW[8192]; reused for reduction
    float* sN = pool;
    float* sW = pool + 4096;
    const int t = threadIdx.x;
    const int i0 = blockIdx.x * 32;
    const int c0 = blockIdx.y * 64;
#pragma unroll
    for (int k = 0; k < 4; k++) {
        int q = t + k * 256;
        ((float4*)sN)[q] = ((const float4*)(nodes + (size_t)i0 * FIN))[q];
    }
#pragma unroll
    for (int k = 0; k < 8; k++) {
        int idx = t + k * 256;
        int f = idx >> 4, q = idx & 15;
        *(float4*)(sW + f * 64 + q * 4) = *(const float4*)(g_Wc + f * CC + c0 + q * 4);
    }
    __syncthreads();
    const int c = t & 63, rg = t >> 6;
    float acc[8] = {0.f,0.f,0.f,0.f,0.f,0.f,0.f,0.f};
#pragma unroll 4
    for (int f = 0; f < 128; f++) {
        float wv = sW[f * 64 + c];
#pragma unroll
        for (int r = 0; r < 8; r++)
            acc[r] += sN[(rg * 8 + r) * 128 + f] * wv;
    }
#pragma unroll
    for (int r = 0; r < 8; r++)
        g_hidden[(size_t)(i0 + rg * 8 + r) * CC + c0 + c] = acc[r];

    // ---- fused scores: head tiles only (blockIdx.y = h for y < 4) ----
    if (blockIdx.y < 4) {
        const int h = blockIdx.y;
        float ssc = ssrc[h * FO + c];
        float stc = stgt[h * FO + c];
        __syncthreads();                    // done reading sN/sW; reuse pool
        float* sRa = pool;                  // [32][65]
        float* sRb = pool + 32 * 65;        // [32][65]
#pragma unroll
        for (int r = 0; r < 8; r++) {
            sRa[(rg * 8 + r) * 65 + c] = acc[r] * ssc;
            sRb[(rg * 8 + r) * 65 + c] = acc[r] * stc;
        }
        __syncthreads();
        int row = t >> 3, seg = t & 7;
        float s1 = 0.f, s2 = 0.f;
#pragma unroll
        for (int q = 0; q < 8; q++) {
            s1 += sRa[row * 65 + seg * 8 + q];
            s2 += sRb[row * 65 + seg * 8 + q];
        }
#pragma unroll
        for (int o = 4; o > 0; o >>= 1) {
            s1 += __shfl_xor_sync(0xffffffffu, s1, o);
            s2 += __shfl_xor_sync(0xffffffffu, s2, o);
        }
        if (seg == 0) {
            g_A[h * NN + i0 + row] = make_float4(s1, __expf(s1), __expf(0.2f * s1), 0.f);
            g_B[h * NN + i0 + row] = make_float4(s2, __expf(s2), __expf(0.2f * s2), 0.f);
        }
    }
}

// ---------------- K1b: transpose proj -> g_projT fp16 [c][j] ----------------
__global__ void __launch_bounds__(256) k1b_transpose() {
    __shared__ float sT[64 * 65];
    const int t = threadIdx.x;
    const int j0 = blockIdx.x * 64;
    const int c0 = blockIdx.y * 64;
#pragma unroll
    for (int k = 0; k < 4; k++) {
        int idx = t + k * 256;
        int jr = idx >> 4, q = idx & 15;
        float4 v = *(const float4*)(g_hidden + (size_t)(j0 + jr) * CC + c0 + q * 4);
        sT[(q * 4 + 0) * 65 + jr] = v.x;
        sT[(q * 4 + 1) * 65 + jr] = v.y;
        sT[(q * 4 + 2) * 65 + jr] = v.z;
        sT[(q * 4 + 3) * 65 + jr] = v.w;
    }
    __syncthreads();
#pragma unroll
    for (int k = 0; k < 8; k++) {
        int idx = t + k * 256;
        int cr = idx >> 5, p = idx & 31;
        g_projT[(size_t)(c0 + cr) * (NN/2) + (j0 >> 1) + p] =
            packh2(sT[cr * 65 + 2 * p], sT[cr * 65 + 2 * p + 1]);
    }
}

// ---------------- K1d: finalize Z from k5 partials, pack softmax B-params ----------------
__global__ void k1d_bp() {
    int idx = blockIdx.x * 256 + threadIdx.x;   // 16384
    float4 Bv = g_B[idx];
    float z1 = g_Zp[0][0][idx] + g_Zp[1][0][idx] + g_Zp[2][0][idx] + g_Zp[3][0][idx];
    float z2 = g_Zp[0][1][idx] + g_Zp[1][1][idx] + g_Zp[2][1][idx] + g_Zp[3][1][idx];
    float inv = 1.0f / (Bv.y * z1 + Bv.z * z2);
    g_Bp[idx] = make_uint2(packbf2(-Bv.x, Bv.y * inv), packbf2(Bv.z * inv, 0.f));
}

// ---------------- K3: mask -> emask(bf16) + LayerNorm(mask); register-resident rows ----------------
__global__ void __launch_bounds__(512) k3_mask(const float* __restrict__ deg,
                                               const float* __restrict__ bond,
                                               const float* __restrict__ cutp,
                                               float* __restrict__ out_ln) {
    __shared__ float red1[512], red2[512];
    const int i = blockIdx.x;
    const int t = threadIdx.x;
    const float cut = cutp[0];
    const float4* d4 = (const float4*)(deg  + (size_t)i * NN);
    const float4* b4 = (const float4*)(bond + (size_t)i * NN);
    uint2* e2 = (uint2*)(g_em + (size_t)i * (NN/2));
    float4 dv[2], bv[2], mv[2];
    dv[0] = d4[t]; dv[1] = d4[t + 512];
    bv[0] = b4[t]; bv[1] = b4[t + 512];
    float s = 0.f, sq = 0.f;
#pragma unroll
    for (int k = 0; k < 2; k++) {
        int q = t + k * 512;
        mv[k].x = maskf(dv[k].x, bv[k].x, cut);
        mv[k].y = maskf(dv[k].y, bv[k].y, cut);
        mv[k].z = maskf(dv[k].z, bv[k].z, cut);
        mv[k].w = maskf(dv[k].w, bv[k].w, cut);
        uint2 ev;
        ev.x = packbf2(__expf(mv[k].x), __expf(mv[k].y));
        ev.y = packbf2(__expf(mv[k].z), __expf(mv[k].w));
        e2[q] = ev;
        s  += (mv[k].x + mv[k].y) + (mv[k].z + mv[k].w);
        sq += mv[k].x * mv[k].x + mv[k].y * mv[k].y + mv[k].z * mv[k].z + mv[k].w * mv[k].w;
    }
    red1[t] = s; red2[t] = sq;
    __syncthreads();
    for (int o = 256; o > 0; o >>= 1) {
        if (t < o) { red1[t] += red1[t + o]; red2[t] += red2[t + o]; }
        __syncthreads();
    }
    float mu  = red1[0] * (1.f / NN);
    float var = red2[0] * (1.f / NN) - mu * mu;
    float rs  = rsqrtf(var + 1e-5f);
    float4* o4 = (float4*)(out_ln + (size_t)i * NN);
#pragma unroll
    for (int k = 0; k < 2; k++) {
        int q = t + k * 512;
        o4[q] = make_float4((mv[k].x - mu) * rs, (mv[k].y - mu) * rs,
                            (mv[k].z - mu) * rs, (mv[k].w - mu) * rs);
    }
}

// ---------------- K5: partial column sums over 1024-row chunks ----------------
__global__ void __launch_bounds__(256) k5_colsum() {
    __shared__ float4 sA[4 * 256];
    __shared__ float sS1[4 * 8 * 32];
    __shared__ float sS2[4 * 8 * 32];
    const int t = threadIdx.x;
    const int j0 = blockIdx.x * 32;
    const int cb = blockIdx.y;
    const int col = t & 31, seg = t >> 5;
    const int j = j0 + col;
    const __nv_bfloat16* emb = (const __nv_bfloat16*)g_em;
    float thr[4];
#pragma unroll
    for (int h = 0; h < 4; h++) thr[h] = -g_B[h * NN + j].x;
    float S1[4] = {0,0,0,0}, S2[4] = {0,0,0,0};
    for (int c0 = cb * 1024; c0 < cb * 1024 + 1024; c0 += 256) {
        __syncthreads();
#pragma unroll
        for (int k = 0; k < 4; k++) {
            int idx = t + k * 256;
            sA[idx] = g_A[(idx >> 8) * NN + c0 + (idx & 255)];
        }
        __syncthreads();
        const __nv_bfloat16* emp = emb + (size_t)(c0 + seg * 32) * NN + j;
#pragma unroll 8
        for (int s = 0; s < 32; s++) {
            float em = __bfloat162float(emp[(size_t)s * NN]);
#pragma unroll
            for (int h = 0; h < 4; h++) {
                float4 av = sA[h * 256 + seg * 32 + s];
                if (av.x > thr[h]) S1[h] += av.y * em; else S2[h] += av.z * em;
            }
        }
    }
#pragma unroll
    for (int h = 0; h < 4; h++) {
        sS1[(h * 8 + seg) * 32 + col] = S1[h];
        sS2[(h * 8 + seg) * 32 + col] = S2[h];
    }
    __syncthreads();
    if (t < 128) {
        int h = t >> 5, c = t & 31;
        float z1 = 0.f, z2 = 0.f;
#pragma unroll
        for (int s = 0; s < 8; s++) { z1 += sS1[(h * 8 + s) * 32 + c]; z2 += sS2[(h * 8 + s) * 32 + c]; }
        g_Zp[cb][0][h * NN + j0 + c] = z1;
        g_Zp[cb][1][h * NN + j0 + c] = z2;
    }
}

// ---------------- K4: attn @ proj, fp16 m16n8k16, full double-buffer software pipeline ----------------
// Grid (64 i-tiles of 64, 4 j-chunks of 1024), 256 threads. smem 151,552 B (1 CTA/SM):
//   sPT [2][256 rows][36 u32] @ 0       (projT tiles, cp.async double buffer)
//   sW  [2][4][64][36 u32]    @ 73728   (attention weight tiles, double buffer)
//   sAr [4][64] float4        @ 147456
// Per tile: issue cp.async(jt+1) -> compute w(jt+1) into alt buffer -> mma(jt) with NO
// intervening barrier (warps drift; fma w-compute overlaps tensor mma) -> wait+barrier.
#define SPT_OFF 0
#define SW_OFF  73728
#define SAR_OFF 147456
#define SM4_TOT 151552

#define K4_WCOMP(TILE, EMV, WBUF) do {                                              \
    _Pragma("unroll")                                                               \
    for (int h = 0; h < 4; h++) {                                                   \
        uint4 bp = bp4[h * 2048 + jc * 512 + (TILE) * 32 + p];                      \
        __nv_bfloat162 t0  = *(__nv_bfloat162*)&bp.x;                               \
        __nv_bfloat162 t0b = *(__nv_bfloat162*)&bp.y;                               \
        __nv_bfloat162 t1  = *(__nv_bfloat162*)&bp.z;                               \
        __nv_bfloat162 t1b = *(__nv_bfloat162*)&bp.w;                               \
        float thr0 = __low2float(t0), e10 = __high2float(t0), e20 = __low2float(t0b);\
        float thr1 = __low2float(t1), e11 = __high2float(t1), e21 = __low2float(t1b);\
        _Pragma("unroll")                                                           \
        for (int s = 0; s < 8; s++) {                                               \
            float4 av = sAr[h * 64 + iseg * 8 + s];                                 \
            __nv_bfloat162 em2 = *(__nv_bfloat162*)&(EMV)[s];                       \
            float w0 = ((av.x > thr0) ? av.y * e10 : av.z * e20) * __low2float(em2);\
            float w1 = ((av.x > thr1) ? av.y * e11 : av.z * e21) * __high2float(em2);\
            sW[(WBUF) * 9216 + h * 2304 + (iseg * 8 + s) * 36 + p] = packh2(w0, w1);\
        }                                                                           \
    }                                                                               \
} while (0)

#define K4_ISSUE(TILE, PBUF) do {                                                   \
    const uint32_t* ns = gsrc0 + (TILE) * 32;                                       \
    _Pragma("unroll")                                                               \
    for (int k = 0; k < 8; k++)                                                     \
        cpasync16(sdst0 + (PBUF) * 36864 + k * (32 * 144), ns + (size_t)k * 32 * 2048);\
    asm volatile("cp.async.commit_group;" ::: "memory");                            \
} while (0)

#define K4_EMLOAD(TILE, EMV) do {                                                   \
    _Pragma("unroll")                                                               \
    for (int s = 0; s < 8; s++) (EMV)[s] = emrow[(size_t)s * (NN/2) + (TILE) * 32]; \
} while (0)

#define K4_MMA(BUF) do {                                                            \
    _Pragma("unroll")                                                               \
    for (int h = 0; h < 4; h++) {                                                   \
        const uint32_t hA = aA + (BUF) * 36864 + h * 9216;                          \
        const uint32_t hB = aB + (BUF) * 36864 + h * 9216;                          \
        _Pragma("unroll")                                                           \
        for (int kk = 0; kk < 4; kk++) {                                            \
            uint32_t a0, a1, a2, a3, b00, b01, b10, b11, b20, b21, b30, b31;        \
            ldsm4(a0, a1, a2, a3, hA + kk * 32);                                    \
            ldsm4(b00, b01, b10, b11, hB + kk * 32);                                \
            ldsm4(b20, b21, b30, b31, hB + 16 * 144 + kk * 32);                     \
            asm volatile("mma.sync.aligned.m16n8k16.row.col.f32.f16.f16.f32 "       \
                "{%0,%1,%2,%3}, {%4,%5,%6,%7}, {%8,%9}, {%0,%1,%2,%3};"             \
                : "+f"(acc[h][0][0]), "+f"(acc[h][0][1]), "+f"(acc[h][0][2]), "+f"(acc[h][0][3]) \
                : "r"(a0), "r"(a1), "r"(a2), "r"(a3), "r"(b00), "r"(b01));          \
            asm volatile("mma.sync.aligned.m16n8k16.row.col.f32.f16.f16.f32 "       \
                "{%0,%1,%2,%3}, {%4,%5,%6,%7}, {%8,%9}, {%0,%1,%2,%3};"             \
                : "+f"(acc[h][1][0]), "+f"(acc[h][1][1]), "+f"(acc[h][1][2]), "+f"(acc[h][1][3]) \
                : "r"(a0), "r"(a1), "r"(a2), "r"(a3), "r"(b10), "r"(b11));          \
            asm volatile("mma.sync.aligned.m16n8k16.row.col.f32.f16.f16.f32 "       \
                "{%0,%1,%2,%3}, {%4,%5,%6,%7}, {%8,%9}, {%0,%1,%2,%3};"             \
                : "+f"(acc[h][2][0]), "+f"(acc[h][2][1]), "+f"(acc[h][2][2]), "+f"(acc[h][2][3]) \
                : "r"(a0), "r"(a1), "r"(a2), "r"(a3), "r"(b20), "r"(b21));          \
            asm volatile("mma.sync.aligned.m16n8k16.row.col.f32.f16.f16.f32 "       \
                "{%0,%1,%2,%3}, {%4,%5,%6,%7}, {%8,%9}, {%0,%1,%2,%3};"             \
                : "+f"(acc[h][3][0]), "+f"(acc[h][3][1]), "+f"(acc[h][3][2]), "+f"(acc[h][3][3]) \
                : "r"(a0), "r"(a1), "r"(a2), "r"(a3), "r"(b30), "r"(b31));          \
        }                                                                           \
    }                                                                               \
} while (0)

__global__ void __launch_bounds__(256) k4_mma() {
    extern __shared__ char smem[];
    const uint32_t smb = smem_u32(smem);
    uint32_t* sW  = (uint32_t*)(smem + SW_OFF);
    float4*   sAr = (float4*)(smem + SAR_OFF);
    const int t = threadIdx.x;
    const int i0 = blockIdx.x * 64;
    const int jc = blockIdx.y;             // 1024 j per chunk
    const int lane = t & 31, w = t >> 5;
    const int g = lane >> 2, tg = lane & 3;
    const int mi = (w & 3) * 16, ni = (w >> 2) * 32;
    const int p = lane;
    const int iseg = w;

    sAr[t] = g_A[(t >> 6) * NN + i0 + (t & 63)];
    float acc[4][4][4];
#pragma unroll
    for (int h = 0; h < 4; h++)
#pragma unroll
        for (int n = 0; n < 4; n++)
#pragma unroll
            for (int r = 0; r < 4; r++) acc[h][n][r] = 0.f;

    const int sr = t >> 3, sq = t & 7;
    const uint32_t sdst0 = smb + SPT_OFF + sr * 144 + sq * 16;
    const uint32_t* gsrc0 = g_projT + (size_t)sr * 2048 + jc * 512 + sq * 4;

    const uint32_t aA = smb + SW_OFF + (mi + (lane & 15)) * 144 + (lane >> 4) * 16;
    const uint32_t aB = smb + SPT_OFF +
                        (ni + ((lane >> 4) & 1) * 8 + (lane & 7)) * 144 +
                        ((lane >> 3) & 1) * 16;
    const uint32_t* emrow = g_em + (size_t)(i0 + iseg * 8) * (NN/2) + jc * 512 + p;
    const uint4* bp4 = (const uint4*)g_Bp;

    uint32_t emvA[8], emvB[8];

    // ---- prologue: pt(0) -> sPT[0]; w(0) -> sW[0]; em(1) prefetched ----
    K4_ISSUE(0, 0);
    K4_EMLOAD(0, emvA);
    __syncthreads();            // sAr ready
    K4_WCOMP(0, emvA, 0);
    K4_EMLOAD(1, emvB);
    asm volatile("cp.async.wait_group 0;" ::: "memory");
    __syncthreads();            // sW[0], sPT[0] ready

    for (int jt = 0; jt < 16; jt += 2) {
        // ---- even body: mma(jt) from buffers[0]; prepare tile jt+1 in buffers[1] ----
        K4_ISSUE(jt + 1, 1);
        K4_WCOMP(jt + 1, emvB, 1);
        if (jt + 2 < 16) K4_EMLOAD(jt + 2, emvA);
        K4_MMA(0);
        asm volatile("cp.async.wait_group 0;" ::: "memory");
        __syncthreads();

        // ---- odd body: mma(jt+1) from buffers[1]; prepare tile jt+2 in buffers[0] ----
        if (jt + 2 < 16) {
            K4_ISSUE(jt + 2, 0);
            K4_WCOMP(jt + 2, emvA, 0);
            if (jt + 3 < 16) K4_EMLOAD(jt + 3, emvB);
        }
        K4_MMA(1);
        if (jt + 2 < 16) asm volatile("cp.async.wait_group 0;" ::: "memory");
        __syncthreads();
    }

    // ---- store partials ----
    float* pb = g_part + (size_t)jc * NN * 256;
#pragma unroll
    for (int h = 0; h < 4; h++)
#pragma unroll
        for (int nt = 0; nt < 4; nt++) {
            int col = h * 64 + ni + nt * 8 + 2 * tg;
            *(float2*)(pb + (size_t)(i0 + mi + g) * 256 + col) =
                make_float2(acc[h][nt][0], acc[h][nt][1]);
            *(float2*)(pb + (size_t)(i0 + mi + g + 8) * 256 + col) =
                make_float2(acc[h][nt][2], acc[h][nt][3]);
        }
}

// ---------------- K6: reduce partials + skip + ELU ----------------
__global__ void __launch_bounds__(256) k6_epilogue(float* __restrict__ out) {
    int gid = blockIdx.x * 256 + threadIdx.x;    // 262144 float4
    float4 s = make_float4(0.f, 0.f, 0.f, 0.f);
#pragma unroll
    for (int jc = 0; jc < 4; jc++) {
        float4 v = ((const float4*)(g_part + ((size_t)jc << 20)))[gid];
        s.x += v.x; s.y += v.y; s.z += v.z; s.w += v.w;
    }
    int i = gid >> 6, c = (gid & 63) * 4;
    float4 sk = *(const float4*)(g_hidden + (size_t)i * CC + 256 + c);
    float x0 = s.x + sk.x, x1 = s.y + sk.y, x2 = s.z + sk.z, x3 = s.w + sk.w;
    x0 = x0 > 0.f ? x0 : (__expf(x0) - 1.f);
    x1 = x1 > 0.f ? x1 : (__expf(x1) - 1.f);
    x2 = x2 > 0.f ? x2 : (__expf(x2) - 1.f);
    x3 = x3 > 0.f ? x3 : (__expf(x3) - 1.f);
    ((float4*)out)[gid] = make_float4(x0, x1, x2, x3);
}

// ---------------- launcher ----------------
extern "C" void kernel_launch(void* const* d_in, const int* in_sizes, int n_in,
                              void* d_out, int out_size) {
    const float* nodes = (const float*)d_in[0];
    const float* degm  = (const float*)d_in[1];
    // d_in[2] = edges_features_distance (unused by reference)
    const float* bond  = (const float*)d_in[3];
    const float* projp = (const float*)d_in[4];
    const float* ssrc  = (const float*)d_in[5];
    const float* stgt  = (const float*)d_in[6];
    const float* skw   = (const float*)d_in[7];
    const float* cutp  = (const float*)d_in[8];
    float* out = (float*)d_out;

    k0_weights<<<256, 256>>>(projp, skw);
    k1_gemm<<<dim3(128, 8), 256>>>(nodes, ssrc, stgt);
    k1b_transpose<<<dim3(64, 4), 256>>>();
    k3_mask<<<4096, 512>>>(degm, bond, cutp, out + (size_t)NN * 256);
    k5_colsum<<<dim3(128, 4), 256>>>();
    k1d_bp<<<64, 256>>>();

    cudaFuncSetAttribute(k4_mma, cudaFuncAttributeMaxDynamicSharedMemorySize, SM4_TOT);
    k4_mma<<<dim3(64, 4), 256, SM4_TOT>>>();
    k6_epilogue<<<1024, 256>>>(out);
}

// round 15
// speedup vs baseline: 1.1810x; 1.1810x over previous
#include <cuda_runtime.h>
#include <cuda_bf16.h>
#include <cuda_fp16.h>
#include <cstdint>

#define NN 4096
#define FIN 128
#define FO 64
#define HH 4
#define CC 512   // 256 proj cols (h*64+o) + 256 skip cols

// ---------------- scratch (static device globals; no allocation) ----------------
__device__ uint32_t g_em[(size_t)NN * NN / 2];     // exp(mask) bf16 pairs (32 MB)
__device__ float    g_hidden[(size_t)NN * CC];     // [n][c]: c<256 proj, c>=256 skip (8 MB)
__device__ float    g_Wc[FIN * CC];                // combined weights [f][c]
__device__ float4   g_A[HH * NN];                  // per (h,i): a, e^a, e^{0.2a}, -
__device__ float4   g_B[HH * NN];                  // per (h,j): b, e^b, e^{0.2b}, -
__device__ uint32_t g_projT[(size_t)256 * (NN/2)]; // projT fp16 pairs: row c=h*64+f, cols j (2 MB)
__device__ uint2    g_Bp[HH * NN];                 // packed bf16 (thr,e1),(e2,0) per (h,j)
__device__ float    g_Zp[4][2][HH * NN];           // k5 row-chunk partial column sums (512 KB)
__device__ float    g_part[(size_t)4 * NN * 256];  // per-j-chunk partial outputs (16 MB)

// ---------------- helpers ----------------
__device__ __forceinline__ float maskf(float d, float b, float cut) {
    float wdm = d + b;
    return wdm > 0.f ? wdm : (b > cut ? (b + wdm) : -1e9f);
}
__device__ __forceinline__ uint32_t packbf2(float lo, float hi) {
    __nv_bfloat162 p = __floats2bfloat162_rn(lo, hi);
    return *(uint32_t*)&p;
}
__device__ __forceinline__ uint32_t packh2(float lo, float hi) {
    __half2 p = __floats2half2_rn(lo, hi);
    return *(uint32_t*)&p;
}
__device__ __forceinline__ uint32_t smem_u32(const void* p) {
    uint32_t a;
    asm("{ .reg .u64 t; cvta.to.shared.u64 t, %1; cvt.u32.u64 %0, t; }" : "=r"(a) : "l"(p));
    return a;
}
__device__ __forceinline__ void ldsm4(uint32_t& r0, uint32_t& r1, uint32_t& r2, uint32_t& r3,
                                      uint32_t addr) {
    asm volatile("ldmatrix.sync.aligned.m8n8.x4.shared.b16 {%0,%1,%2,%3}, [%4];"
                 : "=r"(r0), "=r"(r1), "=r"(r2), "=r"(r3) : "r"(addr));
}
__device__ __forceinline__ void cpasync16(uint32_t saddr, const void* gaddr) {
    asm volatile("cp.async.cg.shared.global [%0], [%1], 16;" :: "r"(saddr), "l"(gaddr));
}

// ---------------- K0: build combined weight matrix Wc[f][c] ----------------
__global__ void k0_weights(const float* __restrict__ projp, const float* __restrict__ skw) {
    int idx = blockIdx.x * 256 + threadIdx.x;
    int f = idx >> 9, c = idx & 511;
    float v;
    if (c < 256) v = projp[(c >> 6) * (FIN * FO) + f * FO + (c & 63)];
    else         v = skw[(c - 256) * FIN + f];
    g_Wc[idx] = v;
}

// ---------------- K1: hidden = nodes @ Wc; fused per-(h,n) scores for head tiles ----------------
__global__ void __launch_bounds__(256) k1_gemm(const float* __restrict__ nodes,
                                               const float* __restrict__ ssrc,
                                               const float* __restrict__ stgt) {
    __shared__ float pool[12288];          // 48 KB: sN[4096] | sW[8192]; reused for reduction
    float* sN = pool;
    float* sW = pool + 4096;
    const int t = threadIdx.x;
    const int i0 = blockIdx.x * 32;
    const int c0 = blockIdx.y * 64;
#pragma unroll
    for (int k = 0; k < 4; k++) {
        int q = t + k * 256;
        ((float4*)sN)[q] = ((const float4*)(nodes + (size_t)i0 * FIN))[q];
    }
#pragma unroll
    for (int k = 0; k < 8; k++) {
        int idx = t + k * 256;
        int f = idx >> 4, q = idx & 15;
        *(float4*)(sW + f * 64 + q * 4) = *(const float4*)(g_Wc + f * CC + c0 + q * 4);
    }
    __syncthreads();
    const int c = t & 63, rg = t >> 6;
    float acc[8] = {0.f,0.f,0.f,0.f,0.f,0.f,0.f,0.f};
#pragma unroll 4
    for (int f = 0; f < 128; f++) {
        float wv = sW[f * 64 + c];
#pragma unroll
        for (int r = 0; r < 8; r++)
            acc[r] += sN[(rg * 8 + r) * 128 + f] * wv;
    }
#pragma unroll
    for (int r = 0; r < 8; r++)
        g_hidden[(size_t)(i0 + rg * 8 + r) * CC + c0 + c] = acc[r];

    // ---- fused scores: head tiles only (blockIdx.y = h for y < 4) ----
    if (blockIdx.y < 4) {
        const int h = blockIdx.y;
        float ssc = ssrc[h * FO + c];
        float stc = stgt[h * FO + c];
        __syncthreads();                    // done reading sN/sW; reuse pool
        float* sRa = pool;                  // [32][65]
        float* sRb = pool + 32 * 65;        // [32][65]
#pragma unroll
        for (int r = 0; r < 8; r++) {
            sRa[(rg * 8 + r) * 65 + c] = acc[r] * ssc;
            sRb[(rg * 8 + r) * 65 + c] = acc[r] * stc;
        }
        __syncthreads();
        int row = t >> 3, seg = t & 7;
        float s1 = 0.f, s2 = 0.f;
#pragma unroll
        for (int q = 0; q < 8; q++) {
            s1 += sRa[row * 65 + seg * 8 + q];
            s2 += sRb[row * 65 + seg * 8 + q];
        }
#pragma unroll
        for (int o = 4; o > 0; o >>= 1) {
            s1 += __shfl_xor_sync(0xffffffffu, s1, o);
            s2 += __shfl_xor_sync(0xffffffffu, s2, o);
        }
        if (seg == 0) {
            g_A[h * NN + i0 + row] = make_float4(s1, __expf(s1), __expf(0.2f * s1), 0.f);
            g_B[h * NN + i0 + row] = make_float4(s2, __expf(s2), __expf(0.2f * s2), 0.f);
        }
    }
}

// ---------------- K1b: transpose proj -> g_projT fp16 [c][j] ----------------
__global__ void __launch_bounds__(256) k1b_transpose() {
    __shared__ float sT[64 * 65];
    const int t = threadIdx.x;
    const int j0 = blockIdx.x * 64;
    const int c0 = blockIdx.y * 64;
#pragma unroll
    for (int k = 0; k < 4; k++) {
        int idx = t + k * 256;
        int jr = idx >> 4, q = idx & 15;
        float4 v = *(const float4*)(g_hidden + (size_t)(j0 + jr) * CC + c0 + q * 4);
        sT[(q * 4 + 0) * 65 + jr] = v.x;
        sT[(q * 4 + 1) * 65 + jr] = v.y;
        sT[(q * 4 + 2) * 65 + jr] = v.z;
        sT[(q * 4 + 3) * 65 + jr] = v.w;
    }
    __syncthreads();
#pragma unroll
    for (int k = 0; k < 8; k++) {
        int idx = t + k * 256;
        int cr = idx >> 5, p = idx & 31;
        g_projT[(size_t)(c0 + cr) * (NN/2) + (j0 >> 1) + p] =
            packh2(sT[cr * 65 + 2 * p], sT[cr * 65 + 2 * p + 1]);
    }
}

// ---------------- K1d: finalize Z from k5 partials, pack softmax B-params ----------------
__global__ void k1d_bp() {
    int idx = blockIdx.x * 256 + threadIdx.x;   // 16384
    float4 Bv = g_B[idx];
    float z1 = g_Zp[0][0][idx] + g_Zp[1][0][idx] + g_Zp[2][0][idx] + g_Zp[3][0][idx];
    float z2 = g_Zp[0][1][idx] + g_Zp[1][1][idx] + g_Zp[2][1][idx] + g_Zp[3][1][idx];
    float inv = 1.0f / (Bv.y * z1 + Bv.z * z2);
    g_Bp[idx] = make_uint2(packbf2(-Bv.x, Bv.y * inv), packbf2(Bv.z * inv, 0.f));
}

// ---------------- K3: mask -> emask(bf16) + LayerNorm(mask); register-resident rows ----------------
__global__ void __launch_bounds__(512) k3_mask(const float* __restrict__ deg,
                                               const float* __restrict__ bond,
                                               const float* __restrict__ cutp,
                                               float* __restrict__ out_ln) {
    __shared__ float red1[512], red2[512];
    const int i = blockIdx.x;
    const int t = threadIdx.x;
    const float cut = cutp[0];
    const float4* d4 = (const float4*)(deg  + (size_t)i * NN);
    const float4* b4 = (const float4*)(bond + (size_t)i * NN);
    uint2* e2 = (uint2*)(g_em + (size_t)i * (NN/2));
    float4 dv[2], bv[2], mv[2];
    dv[0] = d4[t]; dv[1] = d4[t + 512];
    bv[0] = b4[t]; bv[1] = b4[t + 512];
    float s = 0.f, sq = 0.f;
#pragma unroll
    for (int k = 0; k < 2; k++) {
        int q = t + k * 512;
        mv[k].x = maskf(dv[k].x, bv[k].x, cut);
        mv[k].y = maskf(dv[k].y, bv[k].y, cut);
        mv[k].z = maskf(dv[k].z, bv[k].z, cut);
        mv[k].w = maskf(dv[k].w, bv[k].w, cut);
        uint2 ev;
        ev.x = packbf2(__expf(mv[k].x), __expf(mv[k].y));
        ev.y = packbf2(__expf(mv[k].z), __expf(mv[k].w));
        e2[q] = ev;
        s  += (mv[k].x + mv[k].y) + (mv[k].z + mv[k].w);
        sq += mv[k].x * mv[k].x + mv[k].y * mv[k].y + mv[k].z * mv[k].z + mv[k].w * mv[k].w;
    }
    red1[t] = s; red2[t] = sq;
    __syncthreads();
    for (int o = 256; o > 0; o >>= 1) {
        if (t < o) { red1[t] += red1[t + o]; red2[t] += red2[t + o]; }
        __syncthreads();
    }
    float mu  = red1[0] * (1.f / NN);
    float var = red2[0] * (1.f / NN) - mu * mu;
    float rs  = rsqrtf(var + 1e-5f);
    float4* o4 = (float4*)(out_ln + (size_t)i * NN);
#pragma unroll
    for (int k = 0; k < 2; k++) {
        int q = t + k * 512;
        o4[q] = make_float4((mv[k].x - mu) * rs, (mv[k].y - mu) * rs,
                            (mv[k].z - mu) * rs, (mv[k].w - mu) * rs);
    }
}

// ---------------- K5: partial column sums over 1024-row chunks ----------------
__global__ void __launch_bounds__(256) k5_colsum() {
    __shared__ float4 sA[4 * 256];
    __shared__ float sS1[4 * 8 * 32];
    __shared__ float sS2[4 * 8 * 32];
    const int t = threadIdx.x;
    const int j0 = blockIdx.x * 32;
    const int cb = blockIdx.y;
    const int col = t & 31, seg = t >> 5;
    const int j = j0 + col;
    const __nv_bfloat16* emb = (const __nv_bfloat16*)g_em;
    float thr[4];
#pragma unroll
    for (int h = 0; h < 4; h++) thr[h] = -g_B[h * NN + j].x;
    float S1[4] = {0,0,0,0}, S2[4] = {0,0,0,0};
    for (int c0 = cb * 1024; c0 < cb * 1024 + 1024; c0 += 256) {
        __syncthreads();
#pragma unroll
        for (int k = 0; k < 4; k++) {
            int idx = t + k * 256;
            sA[idx] = g_A[(idx >> 8) * NN + c0 + (idx & 255)];
        }
        __syncthreads();
        const __nv_bfloat16* emp = emb + (size_t)(c0 + seg * 32) * NN + j;
#pragma unroll 8
        for (int s = 0; s < 32; s++) {
            float em = __bfloat162float(emp[(size_t)s * NN]);
#pragma unroll
            for (int h = 0; h < 4; h++) {
                float4 av = sA[h * 256 + seg * 32 + s];
                if (av.x > thr[h]) S1[h] += av.y * em; else S2[h] += av.z * em;
            }
        }
    }
#pragma unroll
    for (int h = 0; h < 4; h++) {
        sS1[(h * 8 + seg) * 32 + col] = S1[h];
        sS2[(h * 8 + seg) * 32 + col] = S2[h];
    }
    __syncthreads();
    if (t < 128) {
        int h = t >> 5, c = t & 31;
        float z1 = 0.f, z2 = 0.f;
#pragma unroll
        for (int s = 0; s < 8; s++) { z1 += sS1[(h * 8 + s) * 32 + c]; z2 += sS2[(h * 8 + s) * 32 + c]; }
        g_Zp[cb][0][h * NN + j0 + c] = z1;
        g_Zp[cb][1][h * NN + j0 + c] = z2;
    }
}

// ---------------- K4: attn @ proj (4 heads), fp16 m16n8k16, cp.async double-buffer ----------------
// (R11's verified-fastest k4: 106us measured.) Grid (64 i-tiles of 64, 4 j-chunks of 1024),
// 256 threads. smem 114,688 B:
//   sPT [2][256 rows c][36 u32] @ 0      (projT tile double buffer; cp.async staged)
//   sW  [4][64 rows][36 u32]    @ 73728  (attention weights, fp16, stride 144B)
//   sAr [4][64] float4          @ 110592
#define SPT_OFF 0
#define SW_OFF  73728
#define SAR_OFF 110592
#define SM4_TOT 114688
__global__ void __launch_bounds__(256) k4_mma() {
    extern __shared__ char smem[];
    const uint32_t smb = smem_u32(smem);
    uint32_t* sW  = (uint32_t*)(smem + SW_OFF);
    float4*   sAr = (float4*)(smem + SAR_OFF);
    const int t = threadIdx.x;
    const int i0 = blockIdx.x * 64;
    const int jc = blockIdx.y;             // 1024 j per chunk
    const int lane = t & 31, w = t >> 5;
    const int g = lane >> 2, tg = lane & 3;
    const int mi = (w & 3) * 16, ni = (w >> 2) * 32;
    const int p = lane;     // j-pair 0..31 (w-gen)
    const int iseg = w;     // warp -> rows iseg*8..+8 (w-gen)

    sAr[t] = g_A[(t >> 6) * NN + i0 + (t & 63)];
    float acc[4][4][4];
#pragma unroll
    for (int h = 0; h < 4; h++)
#pragma unroll
        for (int n = 0; n < 4; n++)
#pragma unroll
            for (int r = 0; r < 4; r++) acc[h][n][r] = 0.f;

    // staging indices for cp.async (8 chunks of 16B per thread)
    const int sr = t >> 3, sq = t & 7;
    const uint32_t sdst0 = smb + SPT_OFF + sr * 144 + sq * 16;
    const uint32_t* gsrc0 = g_projT + (size_t)sr * 2048 + jc * 512 + sq * 4;

    // ldmatrix lane address offsets (bytes)
    const uint32_t aA  = smb + SW_OFF + (mi + (lane & 15)) * 144 + (lane >> 4) * 16;
    const uint32_t aB0 = smb + SPT_OFF +
                         (ni + ((lane >> 4) & 1) * 8 + (lane & 7)) * 144 +
                         ((lane >> 3) & 1) * 16;
    const uint32_t* emrow = g_em + (size_t)(i0 + iseg * 8) * (NN/2) + jc * 512 + p;
    const uint4* bp4 = (const uint4*)g_Bp;

    // prologue: issue tile 0 into buffer 0
#pragma unroll
    for (int k = 0; k < 8; k++)
        cpasync16(sdst0 + k * (32 * 144), gsrc0 + (size_t)k * 32 * 2048);
    asm volatile("cp.async.commit_group;" ::: "memory");

    uint32_t emv[8];
#pragma unroll
    for (int s = 0; s < 8; s++) emv[s] = emrow[(size_t)s * (NN/2)];
    __syncthreads();

    for (int jt = 0; jt < 16; jt++) {
        const int buf = jt & 1;
        // issue next tile into the other buffer
        if (jt < 15) {
            const uint32_t nd = sdst0 + (buf ^ 1) * 36864;
            const uint32_t* ns = gsrc0 + (jt + 1) * 32;
#pragma unroll
            for (int k = 0; k < 8; k++)
                cpasync16(nd + k * (32 * 144), ns + (size_t)k * 32 * 2048);
            asm volatile("cp.async.commit_group;" ::: "memory");
        }
        // ---- w-compute into sW (fp16) ----
#pragma unroll
        for (int h = 0; h < 4; h++) {
            uint4 bp = bp4[h * 2048 + jc * 512 + jt * 32 + p];
            __nv_bfloat162 t0  = *(__nv_bfloat162*)&bp.x;
            __nv_bfloat162 t0b = *(__nv_bfloat162*)&bp.y;
            __nv_bfloat162 t1  = *(__nv_bfloat162*)&bp.z;
            __nv_bfloat162 t1b = *(__nv_bfloat162*)&bp.w;
            float thr0 = __low2float(t0), e10 = __high2float(t0), e20 = __low2float(t0b);
            float thr1 = __low2float(t1), e11 = __high2float(t1), e21 = __low2float(t1b);
#pragma unroll
            for (int s = 0; s < 8; s++) {
                float4 av = sAr[h * 64 + iseg * 8 + s];
                __nv_bfloat162 em2 = *(__nv_bfloat162*)&emv[s];
                float w0 = ((av.x > thr0) ? av.y * e10 : av.z * e20) * __low2float(em2);
                float w1 = ((av.x > thr1) ? av.y * e11 : av.z * e21) * __high2float(em2);
                sW[h * 2304 + (iseg * 8 + s) * 36 + p] = packh2(w0, w1);
            }
        }
        // prefetch em for next tile (hidden under mma phase)
        if (jt < 15) {
#pragma unroll
            for (int s = 0; s < 8; s++) emv[s] = emrow[(size_t)s * (NN/2) + (jt + 1) * 32];
        }
        // current tile's cp.async must be complete before ldmatrix
        if (jt < 15) asm volatile("cp.async.wait_group 1;" ::: "memory");
        else         asm volatile("cp.async.wait_group 0;" ::: "memory");
        __syncthreads();

        // ---- mma phase: ldmatrix fragments + m16n8k16 fp16 ----
        const uint32_t aB = aB0 + buf * 36864;
#pragma unroll
        for (int h = 0; h < 4; h++) {
            const uint32_t hA = aA + h * 9216;
            const uint32_t hB = aB + h * 9216;
#pragma unroll
            for (int kk = 0; kk < 4; kk++) {
                uint32_t a0, a1, a2, a3, b00, b01, b10, b11, b20, b21, b30, b31;
                ldsm4(a0, a1, a2, a3, hA + kk * 32);
                ldsm4(b00, b01, b10, b11, hB + kk * 32);
                ldsm4(b20, b21, b30, b31, hB + 16 * 144 + kk * 32);
                asm volatile(
                    "mma.sync.aligned.m16n8k16.row.col.f32.f16.f16.f32 "
                    "{%0,%1,%2,%3}, {%4,%5,%6,%7}, {%8,%9}, {%0,%1,%2,%3};"
                    : "+f"(acc[h][0][0]), "+f"(acc[h][0][1]), "+f"(acc[h][0][2]), "+f"(acc[h][0][3])
                    : "r"(a0), "r"(a1), "r"(a2), "r"(a3), "r"(b00), "r"(b01));
                asm volatile(
                    "mma.sync.aligned.m16n8k16.row.col.f32.f16.f16.f32 "
                    "{%0,%1,%2,%3}, {%4,%5,%6,%7}, {%8,%9}, {%0,%1,%2,%3};"
                    : "+f"(acc[h][1][0]), "+f"(acc[h][1][1]), "+f"(acc[h][1][2]), "+f"(acc[h][1][3])
                    : "r"(a0), "r"(a1), "r"(a2), "r"(a3), "r"(b10), "r"(b11));
                asm volatile(
                    "mma.sync.aligned.m16n8k16.row.col.f32.f16.f16.f32 "
                    "{%0,%1,%2,%3}, {%4,%5,%6,%7}, {%8,%9}, {%0,%1,%2,%3};"
                    : "+f"(acc[h][2][0]), "+f"(acc[h][2][1]), "+f"(acc[h][2][2]), "+f"(acc[h][2][3])
                    : "r"(a0), "r"(a1), "r"(a2), "r"(a3), "r"(b20), "r"(b21));
                asm volatile(
                    "mma.sync.aligned.m16n8k16.row.col.f32.f16.f16.f32 "
                    "{%0,%1,%2,%3}, {%4,%5,%6,%7}, {%8,%9}, {%0,%1,%2,%3};"
                    : "+f"(acc[h][3][0]), "+f"(acc[h][3][1]), "+f"(acc[h][3][2]), "+f"(acc[h][3][3])
                    : "r"(a0), "r"(a1), "r"(a2), "r"(a3), "r"(b30), "r"(b31));
            }
        }
        __syncthreads();   // all warps done reading sW before next overwrite
    }

    // ---- store partials ----
    float* pb = g_part + (size_t)jc * NN * 256;
#pragma unroll
    for (int h = 0; h < 4; h++)
#pragma unroll
        for (int nt = 0; nt < 4; nt++) {
            int col = h * 64 + ni + nt * 8 + 2 * tg;
            *(float2*)(pb + (size_t)(i0 + mi + g) * 256 + col) =
                make_float2(acc[h][nt][0], acc[h][nt][1]);
            *(float2*)(pb + (size_t)(i0 + mi + g + 8) * 256 + col) =
                make_float2(acc[h][nt][2], acc[h][nt][3]);
        }
}

// ---------------- K6: reduce partials + skip + ELU ----------------
__global__ void __launch_bounds__(256) k6_epilogue(float* __restrict__ out) {
    int gid = blockIdx.x * 256 + threadIdx.x;    // 262144 float4
    float4 s = make_float4(0.f, 0.f, 0.f, 0.f);
#pragma unroll
    for (int jc = 0; jc < 4; jc++) {
        float4 v = ((const float4*)(g_part + ((size_t)jc << 20)))[gid];
        s.x += v.x; s.y += v.y; s.z += v.z; s.w += v.w;
    }
    int i = gid >> 6, c = (gid & 63) * 4;
    float4 sk = *(const float4*)(g_hidden + (size_t)i * CC + 256 + c);
    float x0 = s.x + sk.x, x1 = s.y + sk.y, x2 = s.z + sk.z, x3 = s.w + sk.w;
    x0 = x0 > 0.f ? x0 : (__expf(x0) - 1.f);
    x1 = x1 > 0.f ? x1 : (__expf(x1) - 1.f);
    x2 = x2 > 0.f ? x2 : (__expf(x2) - 1.f);
    x3 = x3 > 0.f ? x3 : (__expf(x3) - 1.f);
    ((float4*)out)[gid] = make_float4(x0, x1, x2, x3);
}

// ---------------- launcher ----------------
extern "C" void kernel_launch(void* const* d_in, const int* in_sizes, int n_in,
                              void* d_out, int out_size) {
    const float* nodes = (const float*)d_in[0];
    const float* degm  = (const float*)d_in[1];
    // d_in[2] = edges_features_distance (unused by reference)
    const float* bond  = (const float*)d_in[3];
    const float* projp = (const float*)d_in[4];
    const float* ssrc  = (const float*)d_in[5];
    const float* stgt  = (const float*)d_in[6];
    const float* skw   = (const float*)d_in[7];
    const float* cutp  = (const float*)d_in[8];
    float* out = (float*)d_out;

    k0_weights<<<256, 256>>>(projp, skw);
    k1_gemm<<<dim3(128, 8), 256>>>(nodes, ssrc, stgt);
    k1b_transpose<<<dim3(64, 4), 256>>>();
    k3_mask<<<4096, 512>>>(degm, bond, cutp, out + (size_t)NN * 256);
    k5_colsum<<<dim3(128, 4), 256>>>();
    k1d_bp<<<64, 256>>>();

    cudaFuncSetAttribute(k4_mma, cudaFuncAttributeMaxDynamicSharedMemorySize, SM4_TOT);
    k4_mma<<<dim3(64, 4), 256, SM4_TOT>>>();
    k6_epilogue<<<1024, 256>>>(out);
}